// round 1
// baseline (speedup 1.0000x reference)
#include <cuda_runtime.h>
#include <math.h>

#define Bq 4
#define Hq 8
#define Tq 4096
#define DHq 128
#define BUCKETS 32
#define BSZ 128
#define HHALF 4
#define SCALE 0.03125f   // (H*DH)^-0.5 = 1024^-0.5

// ---------------- scratch (device globals; no allocation allowed) ----------
__device__ float g_bsum[Bq*Hq*BUCKETS*DHq];   // per-bucket sums of rotated k
__device__ float g_val[Bq*Hq*BUCKETS];        // R max value per bucket row
__device__ int   g_idx[Bq*Hq*BUCKETS];        // R argmax (source bucket)

// rotated time index: heads >= HHALF are rolled by -(BSZ-1) on read
__device__ __forceinline__ int rot_t(int t, bool rolled) {
    return rolled ? ((t + BSZ - 1) & (Tq - 1)) : t;
}

// ============ Kernel 1: per-bucket sums of rotated k =======================
// grid: B*H*BUCKETS blocks, 128 threads (one per dim)
__global__ void bucket_sum_kernel(const float* __restrict__ k) {
    int blk = blockIdx.x;                 // (b*H + h)*BUCKETS + u
    int u  = blk % BUCKETS;
    int bh = blk / BUCKETS;
    int h  = bh % Hq;
    bool rolled = (h >= HHALF);
    int dim = threadIdx.x;
    const float* kb = k + (size_t)bh * Tq * DHq;
    float s = 0.f;
    #pragma unroll 4
    for (int r = 0; r < BSZ; r++) {
        int t = rot_t(u * BSZ + r, rolled);
        s += kb[(size_t)t * DHq + dim];
    }
    g_bsum[(size_t)blk * DHq + dim] = s;
}

// ============ Kernel 2: sort scores -> (idx, val) per bucket ===============
// grid: B*H blocks, 256 threads
__global__ void sort_kernel(const float* __restrict__ k,
                            const float* __restrict__ W) {
    int bh = blockIdx.x;
    int h  = bh % Hq;
    bool rolled = (h >= HHALF);
    int tid = threadIdx.x;

    __shared__ float x[BUCKETS][2*DHq];      // 32 KB
    __shared__ float sc[BUCKETS][BUCKETS];   // 4 KB

    const float* kb = k + (size_t)bh * Tq * DHq;

    // x[u] = [ cumsum(k_rot)[u*BSZ] / (u*BSZ+1) , k_rot[u*BSZ] ]
    if (tid < DHq) {
        int dim = tid;
        float run = 0.f;
        for (int u = 0; u < BUCKETS; u++) {
            int t0 = u * BSZ;
            float kfirst = kb[(size_t)rot_t(t0, rolled) * DHq + dim];
            x[u][dim]       = (run + kfirst) / (float)(t0 + 1);
            x[u][DHq + dim] = kfirst;
            run += g_bsum[((size_t)bh * BUCKETS + u) * DHq + dim];
        }
    }
    __syncthreads();

    // scores[u][v] = leaky_relu( x[u] . W[h][:, v] )
    const float* Wh = W + (size_t)h * 2 * DHq * BUCKETS;
    for (int e0 = tid; e0 < BUCKETS * BUCKETS; e0 += blockDim.x) {
        int u = e0 / BUCKETS, v = e0 % BUCKETS;
        float s = 0.f;
        #pragma unroll 4
        for (int e = 0; e < 2 * DHq; e++)
            s += x[u][e] * Wh[e * BUCKETS + v];
        sc[u][v] = (s > 0.f) ? s : 0.01f * s;   // leaky_relu slope 0.01
    }
    __syncthreads();

    // per-row softmax (full row), then strict-lower-tri max/argmax
    if (tid < BUCKETS) {
        int u = tid;
        float m = -INFINITY;
        for (int v = 0; v < BUCKETS; v++) m = fmaxf(m, sc[u][v]);
        float sum = 0.f;
        for (int v = 0; v < BUCKETS; v++) sum += expf(sc[u][v] - m);
        float best = 0.f; int bi = 0;
        for (int v = 0; v < u; v++) {
            float r = expf(sc[u][v] - m) / sum;
            if (r > best) { best = r; bi = v; }   // first max, like jnp.argmax
        }
        g_val[bh * BUCKETS + u] = best;
        g_idx[bh * BUCKETS + u] = bi;
    }
}

// ============ Kernel 3: per-bucket flash attention =========================
// grid: B*H*BUCKETS blocks, 512 threads. thread = (i = tid>>2, p = tid&3).
// dynamic smem: 2 * 64 * 128 floats = 64 KB  (K tile | V tile, reused for out)
#define TJ 64
__global__ void __launch_bounds__(512, 1)
attn_kernel(const float* __restrict__ q, const float* __restrict__ k,
            const float* __restrict__ v, float* __restrict__ out) {
    extern __shared__ float sbuf[];
    float* ks = sbuf;              // TJ*128
    float* vs = sbuf + TJ * DHq;   // TJ*128

    int blk = blockIdx.x;
    int u  = blk % BUCKETS;
    int bh = blk / BUCKETS;
    int h  = bh % Hq;
    bool rolled  = (h >= HHALF);
    bool lastrot = rolled && (u == BUCKETS - 1);

    int tid = threadIdx.x;
    int i = tid >> 2;        // query row 0..127
    int p = tid & 3;         // dim quarter
    int i_lo = (tid & ~31) >> 2;          // smallest i in this warp
    int i_hi = i_lo + 7;                  // largest i in this warp

    int   src  = g_idx[bh * BUCKETS + u];
    float sval = g_val[bh * BUCKETS + u];

    const float* qb = q + (size_t)bh * Tq * DHq;
    const float* kb = k + (size_t)bh * Tq * DHq;
    const float* vb = v + (size_t)bh * Tq * DHq;

    // rotated dim order (bank-conflict-free): float4 slot c4 -> row offset off4
    int off4[8];
    float4 qv[8];
    {
        int tqi = rot_t(u * BSZ + i, rolled);
        const float4* qrow = (const float4*)(qb + (size_t)tqi * DHq);
        #pragma unroll
        for (int c4 = 0; c4 < 8; c4++) {
            int d4 = ((c4 + 2 * p) & 7) + p * 8;
            off4[c4] = d4;
            qv[c4] = qrow[d4];
        }
    }

    float acc[32];
    #pragma unroll
    for (int c = 0; c < 32; c++) acc[c] = 0.f;
    float m = -INFINITY, l = 0.f;

    for (int tile = 0; tile < 2 * BSZ / TJ; tile++) {
        int j0 = tile * TJ;
        __syncthreads();
        // stage K/V tile: keys j0..j0+63.  j<BSZ -> sval * bucket[src]; else own bucket
        for (int e = tid; e < TJ * DHq; e += 512) {
            int r = e >> 7, dim = e & 127;
            int jg = j0 + r;
            int sb; float scl; int jj;
            if (jg < BSZ) { sb = src; scl = sval; jj = jg; }
            else          { sb = u;   scl = 1.f;  jj = jg - BSZ; }
            size_t off = (size_t)rot_t(sb * BSZ + jj, rolled) * DHq + dim;
            ks[e] = scl * kb[off];
            vs[e] = scl * vb[off];
        }
        __syncthreads();

        for (int r = 0; r < TJ; r++) {
            int jg = j0 + r;
            // warp-uniform skip of fully-masked keys
            bool warp_skip;
            if (lastrot && jg <= BSZ) warp_skip = (i_lo != 0);
            else if (jg >= BSZ)       warp_skip = (i_hi < jg - BSZ);
            else                      warp_skip = false;
            if (warp_skip) continue;

            const float4* kr4 = (const float4*)(ks + r * DHq);
            float s = 0.f;
            #pragma unroll
            for (int c4 = 0; c4 < 8; c4++) {
                float4 kk = kr4[off4[c4]];
                s += qv[c4].x * kk.x + qv[c4].y * kk.y
                   + qv[c4].z * kk.z + qv[c4].w * kk.w;
            }
            // partner reduce (lanes differing in bits 0-1 share i -> uniform mask)
            s += __shfl_xor_sync(0xffffffffu, s, 1);
            s += __shfl_xor_sync(0xffffffffu, s, 2);

            bool vis;
            if (lastrot) vis = (jg <= BSZ) ? (i == 0) : (i >= jg - BSZ);
            else         vis = (jg < BSZ) || (i >= jg - BSZ);
            if (!vis) continue;

            float scd = s * SCALE;
            const float4* vr4 = (const float4*)(vs + r * DHq);
            if (scd > m) {
                float corr = __expf(m - scd);   // m=-inf first time -> 0
                m = scd;
                l = l * corr + 1.f;
                #pragma unroll
                for (int c4 = 0; c4 < 8; c4++) {
                    float4 vv = vr4[off4[c4]];
                    acc[c4*4+0] = acc[c4*4+0] * corr + vv.x;
                    acc[c4*4+1] = acc[c4*4+1] * corr + vv.y;
                    acc[c4*4+2] = acc[c4*4+2] * corr + vv.z;
                    acc[c4*4+3] = acc[c4*4+3] * corr + vv.w;
                }
            } else {
                float pv = __expf(scd - m);
                l += pv;
                #pragma unroll
                for (int c4 = 0; c4 < 8; c4++) {
                    float4 vv = vr4[off4[c4]];
                    acc[c4*4+0] += pv * vv.x;
                    acc[c4*4+1] += pv * vv.y;
                    acc[c4*4+2] += pv * vv.z;
                    acc[c4*4+3] += pv * vv.w;
                }
            }
        }
    }

    // normalize, stage to smem (reuses the full 64 KB = exactly 128x128 fp32)
    float invl = 1.f / l;
    __syncthreads();
    float4* os4 = (float4*)sbuf;
    #pragma unroll
    for (int c4 = 0; c4 < 8; c4++) {
        os4[i * 32 + off4[c4]] = make_float4(acc[c4*4+0] * invl,
                                             acc[c4*4+1] * invl,
                                             acc[c4*4+2] * invl,
                                             acc[c4*4+3] * invl);
    }
    __syncthreads();

    // coalesced store with inverse rotation (roll back by +(BSZ-1))
    for (int e = tid; e < BSZ * DHq; e += 512) {
        int r = e >> 7, dim = e & 127;
        int tf = rot_t(u * BSZ + r, rolled);   // inverse of read-side roll
        out[((size_t)bh * Tq + tf) * DHq + dim] = sbuf[e];
    }
}

// ================================ launch ===================================
extern "C" void kernel_launch(void* const* d_in, const int* in_sizes, int n_in,
                              void* d_out, int out_size) {
    const float* q = (const float*)d_in[0];
    const float* k = (const float*)d_in[1];
    const float* v = (const float*)d_in[2];
    const float* W = (const float*)d_in[3];   // (1,H,2*DH,BUCKETS)
    float* out = (float*)d_out;

    cudaFuncSetAttribute(attn_kernel,
                         cudaFuncAttributeMaxDynamicSharedMemorySize,
                         2 * TJ * DHq * (int)sizeof(float));

    bucket_sum_kernel<<<Bq*Hq*BUCKETS, 128>>>(k);
    sort_kernel<<<Bq*Hq, 256>>>(k, W);
    attn_kernel<<<Bq*Hq*BUCKETS, 512, 2*TJ*DHq*(int)sizeof(float)>>>(q, k, v, out);
}

// round 3
// speedup vs baseline: 2.5199x; 2.5199x over previous
#include <cuda_runtime.h>
#include <math.h>
#include <stdint.h>

#define Bq 4
#define Hq 8
#define Tq 4096
#define DHq 128
#define BUCKETS 32
#define BSZ 128
#define HHALF 4
// (H*DH)^-0.5 * log2(e): S computed directly in log2 domain
#define QSCALE (0.03125f * 1.4426950408889634f)

// ------------------------- device scratch ---------------------------------
__device__ float g_bsum[Bq*Hq*BUCKETS*DHq];
__device__ float g_val[Bq*Hq*BUCKETS];
__device__ int   g_idx[Bq*Hq*BUCKETS];

__device__ __forceinline__ int rot_t(int t, bool rolled) {
    return rolled ? ((t + BSZ - 1) & (Tq - 1)) : t;
}
__device__ __forceinline__ float f2tf32f(float f) {
    uint32_t r;
    asm("cvt.rna.tf32.f32 %0, %1;" : "=r"(r) : "f"(f));
    return __uint_as_float(r);
}
__device__ __forceinline__ float ex2f(float x) {
    float r;
    asm("ex2.approx.ftz.f32 %0, %1;" : "=f"(r) : "f"(x));
    return r;
}
// D += A(16x8 tf32, row) * B(8x8 tf32, col)
__device__ __forceinline__ void mma8(float* d, const float* a, const float* b) {
    asm volatile(
        "mma.sync.aligned.m16n8k8.row.col.f32.tf32.tf32.f32 "
        "{%0,%1,%2,%3}, {%4,%5,%6,%7}, {%8,%9}, {%0,%1,%2,%3};"
        : "+f"(d[0]), "+f"(d[1]), "+f"(d[2]), "+f"(d[3])
        : "r"(__float_as_uint(a[0])), "r"(__float_as_uint(a[1])),
          "r"(__float_as_uint(a[2])), "r"(__float_as_uint(a[3])),
          "r"(__float_as_uint(b[0])), "r"(__float_as_uint(b[1])));
}

// ============ Kernel 1: per-bucket sums of rotated k =======================
__global__ void bucket_sum_kernel(const float* __restrict__ k) {
    int blk = blockIdx.x;
    int u  = blk % BUCKETS;
    int bh = blk / BUCKETS;
    int h  = bh % Hq;
    bool rolled = (h >= HHALF);
    int dim = threadIdx.x & 127;
    int qtr = threadIdx.x >> 7;
    __shared__ float part[512];
    const float* kb = k + (size_t)bh * Tq * DHq;
    float s = 0.f;
    #pragma unroll 8
    for (int r = qtr * 32; r < qtr * 32 + 32; r++) {
        int t = rot_t(u * BSZ + r, rolled);
        s += kb[(size_t)t * DHq + dim];
    }
    part[threadIdx.x] = s;
    __syncthreads();
    if (threadIdx.x < 128)
        g_bsum[(size_t)blk * DHq + threadIdx.x] =
            part[threadIdx.x] + part[128 + threadIdx.x] +
            part[256 + threadIdx.x] + part[384 + threadIdx.x];
}

// ============ Kernel 2: sort scores -> (idx, val) per bucket ===============
__global__ void sort_kernel(const float* __restrict__ k,
                            const float* __restrict__ W) {
    int bh = blockIdx.x;
    int h  = bh % Hq;
    bool rolled = (h >= HHALF);
    int tid = threadIdx.x;

    __shared__ float x[BUCKETS][2*DHq];
    __shared__ float sc[BUCKETS][BUCKETS];

    const float* kb = k + (size_t)bh * Tq * DHq;

    if (tid < DHq) {
        int dim = tid;
        float run = 0.f;
        for (int u = 0; u < BUCKETS; u++) {
            int t0 = u * BSZ;
            float kfirst = kb[(size_t)rot_t(t0, rolled) * DHq + dim];
            x[u][dim]       = (run + kfirst) / (float)(t0 + 1);
            x[u][DHq + dim] = kfirst;
            run += g_bsum[((size_t)bh * BUCKETS + u) * DHq + dim];
        }
    }
    __syncthreads();

    const float* Wh = W + (size_t)h * 2 * DHq * BUCKETS;
    for (int e0 = tid; e0 < BUCKETS * BUCKETS; e0 += blockDim.x) {
        int u = e0 / BUCKETS, v = e0 % BUCKETS;
        float s = 0.f;
        #pragma unroll 4
        for (int e = 0; e < 2 * DHq; e++)
            s += x[u][e] * Wh[e * BUCKETS + v];
        sc[u][v] = (s > 0.f) ? s : 0.01f * s;
    }
    __syncthreads();

    if (tid < BUCKETS) {
        int u = tid;
        float m = -INFINITY;
        for (int v = 0; v < BUCKETS; v++) m = fmaxf(m, sc[u][v]);
        float sum = 0.f;
        for (int v = 0; v < BUCKETS; v++) sum += expf(sc[u][v] - m);
        float best = 0.f; int bi = 0;
        for (int v = 0; v < u; v++) {
            float r = expf(sc[u][v] - m) / sum;
            if (r > best) { best = r; bi = v; }
        }
        g_val[bh * BUCKETS + u] = best;
        g_idx[bh * BUCKETS + u] = bi;
    }
}

// ============ Kernel 3: per-bucket attention with mma.sync tf32 ============
// 256 threads = 8 warps: rg = wid&3 (query-row group of 32), cg = wid>>2.
// smem (floats):  Q[128][132] | K[64][132] | V[64][136] | P[128][68] | psum[256]
#define PADQ 132
#define PADK 132
#define PADV 136
#define PADP 68
#define OFF_Q  0
#define OFF_K  (OFF_Q + 128*PADQ)
#define OFF_V  (OFF_K + 64*PADK)
#define OFF_P  (OFF_V + 64*PADV)
#define OFF_PS (OFF_P + 128*PADP)
#define SMEM_FLOATS (OFF_PS + 256)
#define SMEM_BYTES (SMEM_FLOATS * 4)

__global__ void __launch_bounds__(256, 1)
attn_kernel(const float* __restrict__ q, const float* __restrict__ k,
            const float* __restrict__ v, float* __restrict__ out) {
    extern __shared__ float sm[];

    int blk = blockIdx.x;
    int u  = blk % BUCKETS;
    int bh = blk / BUCKETS;
    int h  = bh % Hq;
    bool rolled  = (h >= HHALF);
    bool lastrot = rolled && (u == BUCKETS - 1);

    int tid  = threadIdx.x;
    int wid  = tid >> 5;
    int lane = tid & 31;
    int rg = wid & 3;      // query rows [rg*32, rg*32+32)
    int cg = wid >> 1 >> 1; // 0/1
    int g  = lane >> 2;    // 0..7
    int c  = lane & 3;     // 0..3

    int   src  = g_idx[bh * BUCKETS + u];
    float sval = g_val[bh * BUCKETS + u];

    const float* qb = q + (size_t)bh * Tq * DHq;
    const float* kb = k + (size_t)bh * Tq * DHq;
    const float* vb = v + (size_t)bh * Tq * DHq;

    // ---- stage Q (pre-scaled into log2 domain, tf32-rounded) ----
    #pragma unroll 4
    for (int e = tid; e < BSZ * DHq; e += 256) {
        int i = e >> 7, d = e & 127;
        int tq = rot_t(u * BSZ + i, rolled);
        sm[OFF_Q + i * PADQ + d] = f2tf32f(qb[(size_t)tq * DHq + d] * QSCALE);
    }

    float accO[64];                      // 2 m-tiles x 8 n-tiles x 4
    #pragma unroll
    for (int x = 0; x < 64; x++) accO[x] = 0.f;
    float rsum[4] = {0.f, 0.f, 0.f, 0.f}; // rows g,g+8 (mt0), g+16,g+24 (mt1)

    for (int jt = 0; jt < 4; jt++) {
        __syncthreads();   // prev O-mma done; K/V/P reusable
        // ---- stage K/V tile (64 keys), source per re-sort ----
        #pragma unroll 4
        for (int e = tid; e < 64 * DHq; e += 256) {
            int j = e >> 7, d = e & 127;
            int jg = jt * 64 + j;
            int sb, jj; float scl;
            if (jg < BSZ) { sb = src; jj = jg;       scl = sval; }
            else          { sb = u;   jj = jg - BSZ; scl = 1.f;  }
            size_t off = (size_t)rot_t(sb * BSZ + jj, rolled) * DHq + d;
            sm[OFF_K + j * PADK + d] = f2tf32f(kb[off] * scl);
            sm[OFF_V + j * PADV + d] = f2tf32f(vb[off] * scl);
        }
        __syncthreads();

        // ---- S = Q @ K^T for this warp's 32x32 tile ----
        int jbase_w = jt * 64 + cg * 32;
        bool wskip = lastrot
            ? ((jbase_w + 31 <= BSZ && rg > 0) || (jbase_w - BSZ > rg * 32 + 31))
            : (jbase_w - BSZ > rg * 32 + 31);

        float accS[32];
        #pragma unroll
        for (int x = 0; x < 32; x++) accS[x] = 0.f;

        if (!wskip) {
            #pragma unroll
            for (int ks = 0; ks < 16; ks++) {
                int k0 = ks * 8;
                float a[2][4], b[4][2];
                #pragma unroll
                for (int mt = 0; mt < 2; mt++) {
                    int ar = OFF_Q + (rg * 32 + mt * 16 + g) * PADQ + k0 + c;
                    a[mt][0] = sm[ar];
                    a[mt][1] = sm[ar + 8 * PADQ];
                    a[mt][2] = sm[ar + 4];
                    a[mt][3] = sm[ar + 8 * PADQ + 4];
                }
                #pragma unroll
                for (int nt = 0; nt < 4; nt++) {
                    int br = OFF_K + (cg * 32 + nt * 8 + g) * PADK + k0 + c;
                    b[nt][0] = sm[br];
                    b[nt][1] = sm[br + 4];
                }
                #pragma unroll
                for (int mt = 0; mt < 2; mt++)
                    #pragma unroll
                    for (int nt = 0; nt < 4; nt++)
                        mma8(accS + (mt * 4 + nt) * 4, a[mt], b[nt]);
            }
        }

        // ---- epilogue: mask + exp2 + tf32 round, write P, row sums ----
        #pragma unroll
        for (int mt = 0; mt < 2; mt++) {
            #pragma unroll
            for (int nt = 0; nt < 4; nt++) {
                float* ap = accS + (mt * 4 + nt) * 4;
                int ib   = rg * 32 + mt * 16;
                int jmin = jt * 64 + cg * 32 + nt * 8;
                bool fm = lastrot
                    ? ((jmin + 7 <= BSZ && ib > 0) || (jmin - BSZ > ib + 15))
                    : (jmin - BSZ > ib + 15);
                float p0 = 0.f, p1 = 0.f, p2 = 0.f, p3 = 0.f;
                if (!fm) {
                    int r0 = ib + g, r1 = r0 + 8;
                    int j0 = jmin + 2 * c, j1 = j0 + 1;
                    bool v00, v01, v10, v11;
                    if (lastrot) {
                        v00 = (j0 <= BSZ) ? (r0 == 0) : (r0 >= j0 - BSZ);
                        v01 = (j1 <= BSZ) ? (r0 == 0) : (r0 >= j1 - BSZ);
                        v10 = (j0 <= BSZ) ? (r1 == 0) : (r1 >= j0 - BSZ);
                        v11 = (j1 <= BSZ) ? (r1 == 0) : (r1 >= j1 - BSZ);
                    } else {
                        v00 = (j0 < BSZ) || (r0 >= j0 - BSZ);
                        v01 = (j1 < BSZ) || (r0 >= j1 - BSZ);
                        v10 = (j0 < BSZ) || (r1 >= j0 - BSZ);
                        v11 = (j1 < BSZ) || (r1 >= j1 - BSZ);
                    }
                    p0 = v00 ? f2tf32f(ex2f(ap[0])) : 0.f;
                    p1 = v01 ? f2tf32f(ex2f(ap[1])) : 0.f;
                    p2 = v10 ? f2tf32f(ex2f(ap[2])) : 0.f;
                    p3 = v11 ? f2tf32f(ex2f(ap[3])) : 0.f;
                    rsum[mt * 2 + 0] += p0 + p1;
                    rsum[mt * 2 + 1] += p2 + p3;
                }
                int pc = cg * 32 + nt * 8 + 2 * c;
                int pr0 = rg * 32 + mt * 16 + g;
                *(float2*)&sm[OFF_P + pr0 * PADP + pc]       = make_float2(p0, p1);
                *(float2*)&sm[OFF_P + (pr0 + 8) * PADP + pc] = make_float2(p2, p3);
            }
        }
        __syncthreads();

        // ---- O += P @ V (warp: 32 rows x 64 dims, cols cg*64..) ----
        bool oskip = lastrot
            ? ((jt * 64 + 63 <= BSZ && rg > 0) ||
               (jt * 64 >= BSZ && jt * 64 - BSZ > rg * 32 + 31))
            : (jt * 64 >= BSZ && jt * 64 - BSZ > rg * 32 + 31);
        if (!oskip) {
            #pragma unroll
            for (int ks = 0; ks < 8; ks++) {
                int k0 = ks * 8;
                float a[2][4];
                #pragma unroll
                for (int mt = 0; mt < 2; mt++) {
                    int ar = OFF_P + (rg * 32 + mt * 16 + g) * PADP + k0 + c;
                    a[mt][0] = sm[ar];
                    a[mt][1] = sm[ar + 8 * PADP];
                    a[mt][2] = sm[ar + 4];
                    a[mt][3] = sm[ar + 8 * PADP + 4];
                }
                #pragma unroll
                for (int nt = 0; nt < 8; nt++) {
                    float b[2];
                    int br = OFF_V + (k0 + c) * PADV + cg * 64 + nt * 8 + g;
                    b[0] = sm[br];
                    b[1] = sm[br + 4 * PADV];
                    mma8(accO + (0 * 8 + nt) * 4, a[0], b);
                    mma8(accO + (1 * 8 + nt) * 4, a[1], b);
                }
            }
        }
    }

    // ---- finalize row sums -> linv ----
    #pragma unroll
    for (int x = 0; x < 4; x++) {
        rsum[x] += __shfl_xor_sync(0xffffffffu, rsum[x], 1);
        rsum[x] += __shfl_xor_sync(0xffffffffu, rsum[x], 2);
    }
    __syncthreads();   // all O-mma done (P region done being read)
    if (c == 0) {
        #pragma unroll
        for (int x = 0; x < 4; x++) {
            int row = rg * 32 + (x >> 1) * 16 + g + (x & 1) * 8;
            sm[OFF_PS + cg * 128 + row] = rsum[x];
        }
    }
    __syncthreads();
    if (tid < 128)
        sm[OFF_PS + tid] = 1.f / (sm[OFF_PS + tid] + sm[OFF_PS + 128 + tid]);
    __syncthreads();

    // ---- normalize + store (rotation folded into scatter) ----
    float il[4];
    #pragma unroll
    for (int x = 0; x < 4; x++)
        il[x] = sm[OFF_PS + rg * 32 + (x >> 1) * 16 + g + (x & 1) * 8];

    float* ob = out + (size_t)bh * Tq * DHq;
    #pragma unroll
    for (int mt = 0; mt < 2; mt++) {
        int i0 = rg * 32 + mt * 16 + g;
        int t0 = rot_t(u * BSZ + i0, rolled);
        int t1 = rot_t(u * BSZ + i0 + 8, rolled);
        #pragma unroll
        for (int nt = 0; nt < 8; nt++) {
            float* ap = accO + (mt * 8 + nt) * 4;
            int d = cg * 64 + nt * 8 + 2 * c;
            *(float2*)&ob[(size_t)t0 * DHq + d] =
                make_float2(ap[0] * il[mt * 2], ap[1] * il[mt * 2]);
            *(float2*)&ob[(size_t)t1 * DHq + d] =
                make_float2(ap[2] * il[mt * 2 + 1], ap[3] * il[mt * 2 + 1]);
        }
    }
}

// ================================ launch ===================================
extern "C" void kernel_launch(void* const* d_in, const int* in_sizes, int n_in,
                              void* d_out, int out_size) {
    const float* q = (const float*)d_in[0];
    const float* k = (const float*)d_in[1];
    const float* v = (const float*)d_in[2];
    const float* W = (const float*)d_in[3];
    float* out = (float*)d_out;

    cudaFuncSetAttribute(attn_kernel,
                         cudaFuncAttributeMaxDynamicSharedMemorySize, SMEM_BYTES);

    bucket_sum_kernel<<<Bq*Hq*BUCKETS, 512>>>(k);
    sort_kernel<<<Bq*Hq, 256>>>(k, W);
    attn_kernel<<<Bq*Hq*BUCKETS, 256, SMEM_BYTES>>>(q, k, v, out);
}

// round 4
// speedup vs baseline: 2.5861x; 1.0263x over previous
#include <cuda_runtime.h>
#include <math.h>
#include <stdint.h>

#define Bq 4
#define Hq 8
#define Tq 4096
#define DHq 128
#define BUCKETS 32
#define BSZ 128
#define HHALF 4
// (H*DH)^-0.5 * log2(e): S computed directly in log2 domain
#define QSCALE (0.03125f * 1.4426950408889634f)

// ------------------------- device scratch ---------------------------------
__device__ float g_bsum[Bq*Hq*BUCKETS*DHq];
__device__ float g_val[Bq*Hq*BUCKETS];
__device__ int   g_idx[Bq*Hq*BUCKETS];

__device__ __forceinline__ int rot_t(int t, bool rolled) {
    return rolled ? ((t + BSZ - 1) & (Tq - 1)) : t;
}
__device__ __forceinline__ float f2tf32f(float f) {
    uint32_t r;
    asm("cvt.rna.tf32.f32 %0, %1;" : "=r"(r) : "f"(f));
    return __uint_as_float(r);
}
__device__ __forceinline__ float ex2f(float x) {
    float r;
    asm("ex2.approx.ftz.f32 %0, %1;" : "=f"(r) : "f"(x));
    return r;
}
// D += A(16x8 tf32, row) * B(8x8 tf32, col)
__device__ __forceinline__ void mma8(float* d, const float* a, const float* b) {
    asm volatile(
        "mma.sync.aligned.m16n8k8.row.col.f32.tf32.tf32.f32 "
        "{%0,%1,%2,%3}, {%4,%5,%6,%7}, {%8,%9}, {%0,%1,%2,%3};"
        : "+f"(d[0]), "+f"(d[1]), "+f"(d[2]), "+f"(d[3])
        : "r"(__float_as_uint(a[0])), "r"(__float_as_uint(a[1])),
          "r"(__float_as_uint(a[2])), "r"(__float_as_uint(a[3])),
          "r"(__float_as_uint(b[0])), "r"(__float_as_uint(b[1])));
}

// ============ Kernel 1: per-bucket sums of rotated k =======================
__global__ void bucket_sum_kernel(const float* __restrict__ k) {
    int blk = blockIdx.x;
    int u  = blk % BUCKETS;
    int bh = blk / BUCKETS;
    int h  = bh % Hq;
    bool rolled = (h >= HHALF);
    int dim = threadIdx.x & 127;
    int qtr = threadIdx.x >> 7;
    __shared__ float part[512];
    const float* kb = k + (size_t)bh * Tq * DHq;
    float s = 0.f;
    #pragma unroll 8
    for (int r = qtr * 32; r < qtr * 32 + 32; r++) {
        int t = rot_t(u * BSZ + r, rolled);
        s += kb[(size_t)t * DHq + dim];
    }
    part[threadIdx.x] = s;
    __syncthreads();
    if (threadIdx.x < 128)
        g_bsum[(size_t)blk * DHq + threadIdx.x] =
            part[threadIdx.x] + part[128 + threadIdx.x] +
            part[256 + threadIdx.x] + part[384 + threadIdx.x];
}

// ============ Kernel 2: sort scores -> (idx, val) per bucket ===============
__global__ void sort_kernel(const float* __restrict__ k,
                            const float* __restrict__ W) {
    int bh = blockIdx.x;
    int h  = bh % Hq;
    bool rolled = (h >= HHALF);
    int tid = threadIdx.x;

    __shared__ float x[BUCKETS][2*DHq];
    __shared__ float sc[BUCKETS][BUCKETS];

    const float* kb = k + (size_t)bh * Tq * DHq;

    if (tid < DHq) {
        int dim = tid;
        float run = 0.f;
        for (int u = 0; u < BUCKETS; u++) {
            int t0 = u * BSZ;
            float kfirst = kb[(size_t)rot_t(t0, rolled) * DHq + dim];
            x[u][dim]       = (run + kfirst) / (float)(t0 + 1);
            x[u][DHq + dim] = kfirst;
            run += g_bsum[((size_t)bh * BUCKETS + u) * DHq + dim];
        }
    }
    __syncthreads();

    const float* Wh = W + (size_t)h * 2 * DHq * BUCKETS;
    for (int e0 = tid; e0 < BUCKETS * BUCKETS; e0 += blockDim.x) {
        int u = e0 / BUCKETS, v = e0 % BUCKETS;
        float s = 0.f;
        #pragma unroll 4
        for (int e = 0; e < 2 * DHq; e++)
            s += x[u][e] * Wh[e * BUCKETS + v];
        sc[u][v] = (s > 0.f) ? s : 0.01f * s;
    }
    __syncthreads();

    if (tid < BUCKETS) {
        int u = tid;
        float m = -INFINITY;
        for (int v = 0; v < BUCKETS; v++) m = fmaxf(m, sc[u][v]);
        float sum = 0.f;
        for (int v = 0; v < BUCKETS; v++) sum += expf(sc[u][v] - m);
        float best = 0.f; int bi = 0;
        for (int v = 0; v < u; v++) {
            float r = expf(sc[u][v] - m) / sum;
            if (r > best) { best = r; bi = v; }
        }
        g_val[bh * BUCKETS + u] = best;
        g_idx[bh * BUCKETS + u] = bi;
    }
}

// ============ Kernel 3: per-bucket attention, 64 q-rows per CTA ============
// 2048 CTAs total (2 per bucket, split by q-row half). 256 thr = 8 warps.
// rg = wid&1 -> local rows [rg*32,+32); cg = wid>>1 in 0..3.
// S warp tile: 32 rows x 8 cols (cols cg*8 within 32-key j-tile).
// O warp tile: 32 rows x 32 dims (dims cg*32), contraction 32 j's.
// smem (floats): Q[64][132] | K[32][132] | V[32][136] | P[64][36] | psum[256]
#define PADQ 132
#define PADK 132
#define PADV 136
#define PADP 36
#define OFF_Q  0
#define OFF_K  (OFF_Q + 64*PADQ)
#define OFF_V  (OFF_K + 32*PADK)
#define OFF_P  (OFF_V + 32*PADV)
#define OFF_PS (OFF_P + 64*PADP)
#define SMEM_FLOATS (OFF_PS + 256)
#define SMEM_BYTES (SMEM_FLOATS * 4)

__global__ void __launch_bounds__(256, 2)
attn_kernel(const float* __restrict__ q, const float* __restrict__ k,
            const float* __restrict__ v, float* __restrict__ out, int base) {
    extern __shared__ float sm[];

    int gi = base + blockIdx.x;        // 0..2047
    int half = gi & 1;                 // which 64 q-rows
    int pair = gi >> 1;                // (b*H+h)*BUCKETS + u
    int u  = pair % BUCKETS;
    int bh = pair / BUCKETS;
    int h  = bh % Hq;
    bool rolled  = (h >= HHALF);
    bool lastrot = rolled && (u == BUCKETS - 1);
    int ib0 = half * 64;               // absolute q-row base

    int tid  = threadIdx.x;
    int wid  = tid >> 5;
    int lane = tid & 31;
    int rg = wid & 1;       // local rows [rg*32, +32)
    int cg = wid >> 1;      // 0..3
    int g  = lane >> 2;     // 0..7
    int c  = lane & 3;      // 0..3

    int   src  = g_idx[bh * BUCKETS + u];
    float sval = g_val[bh * BUCKETS + u];

    const float* qb = q + (size_t)bh * Tq * DHq;
    const float* kb = k + (size_t)bh * Tq * DHq;
    const float* vb = v + (size_t)bh * Tq * DHq;

    // ---- stage Q (64 rows of this half; pre-scaled, tf32) ----
    #pragma unroll 4
    for (int e = tid; e < 64 * DHq; e += 256) {
        int i = e >> 7, d = e & 127;
        int tq = rot_t(u * BSZ + ib0 + i, rolled);
        sm[OFF_Q + i * PADQ + d] = f2tf32f(qb[(size_t)tq * DHq + d] * QSCALE);
    }

    float accO[32];                    // 2 mt x 4 nt x 4
    #pragma unroll
    for (int x = 0; x < 32; x++) accO[x] = 0.f;
    float rsum[4] = {0.f, 0.f, 0.f, 0.f};

    int ib_abs = ib0 + rg * 32;        // absolute base row of warp tile

    for (int jt = 0; jt < 8; jt++) {
        __syncthreads();
        // ---- stage K/V tile (32 keys) ----
        #pragma unroll 4
        for (int e = tid; e < 32 * DHq; e += 256) {
            int j = e >> 7, d = e & 127;
            int jg = jt * 32 + j;
            int sb, jj; float scl;
            if (jg < BSZ) { sb = src; jj = jg;       scl = sval; }
            else          { sb = u;   jj = jg - BSZ; scl = 1.f;  }
            size_t off = (size_t)rot_t(sb * BSZ + jj, rolled) * DHq + d;
            sm[OFF_K + j * PADK + d] = f2tf32f(kb[off] * scl);
            sm[OFF_V + j * PADV + d] = f2tf32f(vb[off] * scl);
        }
        __syncthreads();

        // ---- S = Q @ K^T : warp 32x8 tile ----
        int jbase_w = jt * 32 + cg * 8;
        bool wskip = lastrot
            ? ((jbase_w + 7 <= BSZ && ib_abs > 0) || (jbase_w - BSZ > ib_abs + 31))
            : (jbase_w - BSZ > ib_abs + 31);

        float accS[8];
        #pragma unroll
        for (int x = 0; x < 8; x++) accS[x] = 0.f;

        if (!wskip) {
            #pragma unroll
            for (int ks = 0; ks < 16; ks++) {
                int k0 = ks * 8;
                float a[2][4], b[2];
                #pragma unroll
                for (int mt = 0; mt < 2; mt++) {
                    int ar = OFF_Q + (rg * 32 + mt * 16 + g) * PADQ + k0 + c;
                    a[mt][0] = sm[ar];
                    a[mt][1] = sm[ar + 8 * PADQ];
                    a[mt][2] = sm[ar + 4];
                    a[mt][3] = sm[ar + 8 * PADQ + 4];
                }
                int br = OFF_K + (cg * 8 + g) * PADK + k0 + c;
                b[0] = sm[br];
                b[1] = sm[br + 4];
                mma8(accS + 0, a[0], b);
                mma8(accS + 4, a[1], b);
            }
        }

        // ---- epilogue: mask + exp2 + tf32, write P, row sums ----
        #pragma unroll
        for (int mt = 0; mt < 2; mt++) {
            float* ap = accS + mt * 4;
            int ib   = ib_abs + mt * 16;            // absolute 16-row block base
            int jmin = jbase_w;                     // absolute col base (8 cols)
            bool fm = lastrot
                ? ((jmin + 7 <= BSZ && ib > 0) || (jmin - BSZ > ib + 15))
                : (jmin - BSZ > ib + 15);
            float p0 = 0.f, p1 = 0.f, p2 = 0.f, p3 = 0.f;
            if (!fm) {
                int r0 = ib + g, r1 = r0 + 8;
                int j0 = jmin + 2 * c, j1 = j0 + 1;
                bool v00, v01, v10, v11;
                if (lastrot) {
                    v00 = (j0 <= BSZ) ? (r0 == 0) : (r0 >= j0 - BSZ);
                    v01 = (j1 <= BSZ) ? (r0 == 0) : (r0 >= j1 - BSZ);
                    v10 = (j0 <= BSZ) ? (r1 == 0) : (r1 >= j0 - BSZ);
                    v11 = (j1 <= BSZ) ? (r1 == 0) : (r1 >= j1 - BSZ);
                } else {
                    v00 = (j0 < BSZ) || (r0 >= j0 - BSZ);
                    v01 = (j1 < BSZ) || (r0 >= j1 - BSZ);
                    v10 = (j0 < BSZ) || (r1 >= j0 - BSZ);
                    v11 = (j1 < BSZ) || (r1 >= j1 - BSZ);
                }
                p0 = v00 ? f2tf32f(ex2f(ap[0])) : 0.f;
                p1 = v01 ? f2tf32f(ex2f(ap[1])) : 0.f;
                p2 = v10 ? f2tf32f(ex2f(ap[2])) : 0.f;
                p3 = v11 ? f2tf32f(ex2f(ap[3])) : 0.f;
                rsum[mt * 2 + 0] += p0 + p1;
                rsum[mt * 2 + 1] += p2 + p3;
            }
            int pc  = cg * 8 + 2 * c;               // local col in P
            int pr0 = rg * 32 + mt * 16 + g;        // local row
            *(float2*)&sm[OFF_P + pr0 * PADP + pc]       = make_float2(p0, p1);
            *(float2*)&sm[OFF_P + (pr0 + 8) * PADP + pc] = make_float2(p2, p3);
        }
        __syncthreads();

        // ---- O += P @ V : warp 32 rows x 32 dims, 4 k-steps ----
        int jt0 = jt * 32;
        bool oskip = lastrot
            ? ((jt0 + 31 <= BSZ && ib_abs > 0) || (jt0 - BSZ > ib_abs + 31))
            : (jt0 - BSZ > ib_abs + 31);
        if (!oskip) {
            #pragma unroll
            for (int ks = 0; ks < 4; ks++) {
                int k0 = ks * 8;
                float a[2][4];
                #pragma unroll
                for (int mt = 0; mt < 2; mt++) {
                    int ar = OFF_P + (rg * 32 + mt * 16 + g) * PADP + k0 + c;
                    a[mt][0] = sm[ar];
                    a[mt][1] = sm[ar + 8 * PADP];
                    a[mt][2] = sm[ar + 4];
                    a[mt][3] = sm[ar + 8 * PADP + 4];
                }
                #pragma unroll
                for (int nt = 0; nt < 4; nt++) {
                    float b[2];
                    int br = OFF_V + (k0 + c) * PADV + cg * 32 + nt * 8 + g;
                    b[0] = sm[br];
                    b[1] = sm[br + 4 * PADV];
                    mma8(accO + (0 * 4 + nt) * 4, a[0], b);
                    mma8(accO + (1 * 4 + nt) * 4, a[1], b);
                }
            }
        }
    }

    // ---- finalize row sums -> linv ----
    #pragma unroll
    for (int x = 0; x < 4; x++) {
        rsum[x] += __shfl_xor_sync(0xffffffffu, rsum[x], 1);
        rsum[x] += __shfl_xor_sync(0xffffffffu, rsum[x], 2);
    }
    __syncthreads();
    if (c == 0) {
        #pragma unroll
        for (int x = 0; x < 4; x++) {
            int row = rg * 32 + (x >> 1) * 16 + g + (x & 1) * 8;  // local
            sm[OFF_PS + cg * 64 + row] = rsum[x];
        }
    }
    __syncthreads();
    if (tid < 64)
        sm[OFF_PS + tid] = 1.f / (sm[OFF_PS + tid] + sm[OFF_PS + 64 + tid] +
                                  sm[OFF_PS + 128 + tid] + sm[OFF_PS + 192 + tid]);
    __syncthreads();

    float il[4];
    #pragma unroll
    for (int x = 0; x < 4; x++)
        il[x] = sm[OFF_PS + rg * 32 + (x >> 1) * 16 + g + (x & 1) * 8];

    // ---- normalize + store (rotation folded into scatter) ----
    float* ob = out + (size_t)bh * Tq * DHq;
    #pragma unroll
    for (int mt = 0; mt < 2; mt++) {
        int i0 = ib0 + rg * 32 + mt * 16 + g;     // absolute
        int t0 = rot_t(u * BSZ + i0, rolled);
        int t1 = rot_t(u * BSZ + i0 + 8, rolled);
        #pragma unroll
        for (int nt = 0; nt < 4; nt++) {
            float* ap = accO + (mt * 4 + nt) * 4;
            int d = cg * 32 + nt * 8 + 2 * c;
            *(float2*)&ob[(size_t)t0 * DHq + d] =
                make_float2(ap[0] * il[mt * 2], ap[1] * il[mt * 2]);
            *(float2*)&ob[(size_t)t1 * DHq + d] =
                make_float2(ap[2] * il[mt * 2 + 1], ap[3] * il[mt * 2 + 1]);
        }
    }
}

// ================================ launch ===================================
extern "C" void kernel_launch(void* const* d_in, const int* in_sizes, int n_in,
                              void* d_out, int out_size) {
    const float* q = (const float*)d_in[0];
    const float* k = (const float*)d_in[1];
    const float* v = (const float*)d_in[2];
    const float* W = (const float*)d_in[3];
    float* out = (float*)d_out;

    cudaFuncSetAttribute(attn_kernel,
                         cudaFuncAttributeMaxDynamicSharedMemorySize, SMEM_BYTES);

    bucket_sum_kernel<<<Bq*Hq*BUCKETS, 512>>>(k);
    sort_kernel<<<Bq*Hq, 256>>>(k, W);
    // split: 4 launches/replay puts an attn launch at ncu's capture index
    attn_kernel<<<1024, 256, SMEM_BYTES>>>(q, k, v, out, 0);
    attn_kernel<<<1024, 256, SMEM_BYTES>>>(q, k, v, out, 1024);
}

// round 5
// speedup vs baseline: 4.6932x; 1.8147x over previous
#include <cuda_runtime.h>
#include <cuda_fp16.h>
#include <math.h>
#include <stdint.h>

#define Bq 4
#define Hq 8
#define Tq 4096
#define DHq 128
#define BUCKETS 32
#define BSZ 128
#define HHALF 4
// (H*DH)^-0.5 * log2(e): S computed directly in log2 domain
#define QSCALE (0.03125f * 1.4426950408889634f)

// ------------------------- device scratch ---------------------------------
__device__ float g_bsum[Bq*Hq*BUCKETS*DHq];
__device__ float g_val[Bq*Hq*BUCKETS];
__device__ int   g_idx[Bq*Hq*BUCKETS];

__device__ __forceinline__ int rot_t(int t, bool rolled) {
    return rolled ? ((t + BSZ - 1) & (Tq - 1)) : t;
}
__device__ __forceinline__ float ex2f(float x) {
    float r;
    asm("ex2.approx.ftz.f32 %0, %1;" : "=f"(r) : "f"(x));
    return r;
}
__device__ __forceinline__ uint32_t pack_h2(float a, float b) {
    __half2 h = __floats2half2_rn(a, b);
    return *reinterpret_cast<uint32_t*>(&h);
}
__device__ __forceinline__ float2 unpack_h2(uint32_t u) {
    __half2 h = *reinterpret_cast<__half2*>(&u);
    return __half22float2(h);
}
__device__ __forceinline__ uint32_t smem_u32(const void* p) {
    uint32_t a;
    asm("{ .reg .u64 t; cvta.to.shared.u64 t, %1; cvt.u32.u64 %0, t; }"
        : "=r"(a) : "l"(p));
    return a;
}
__device__ __forceinline__ void ldsm4(uint32_t* r, uint32_t addr) {
    asm volatile("ldmatrix.sync.aligned.m8n8.x4.shared.b16 {%0,%1,%2,%3}, [%4];"
        : "=r"(r[0]), "=r"(r[1]), "=r"(r[2]), "=r"(r[3]) : "r"(addr));
}
__device__ __forceinline__ void ldsm4t(uint32_t* r, uint32_t addr) {
    asm volatile("ldmatrix.sync.aligned.m8n8.x4.trans.shared.b16 {%0,%1,%2,%3}, [%4];"
        : "=r"(r[0]), "=r"(r[1]), "=r"(r[2]), "=r"(r[3]) : "r"(addr));
}
// D += A(16x16 f16) * B(16x8 f16), fp32 accum
__device__ __forceinline__ void mma16816(float* d, const uint32_t* a, const uint32_t* b) {
    asm volatile("mma.sync.aligned.m16n8k16.row.col.f32.f16.f16.f32 "
        "{%0,%1,%2,%3}, {%4,%5,%6,%7}, {%8,%9}, {%0,%1,%2,%3};"
        : "+f"(d[0]), "+f"(d[1]), "+f"(d[2]), "+f"(d[3])
        : "r"(a[0]), "r"(a[1]), "r"(a[2]), "r"(a[3]), "r"(b[0]), "r"(b[1]));
}

// ============ Kernel 1: per-bucket sums of rotated k =======================
__global__ void bucket_sum_kernel(const float* __restrict__ k) {
    int blk = blockIdx.x;
    int u  = blk % BUCKETS;
    int bh = blk / BUCKETS;
    int h  = bh % Hq;
    bool rolled = (h >= HHALF);
    int dim = threadIdx.x & 127;
    int qtr = threadIdx.x >> 7;
    __shared__ float part[512];
    const float* kb = k + (size_t)bh * Tq * DHq;
    float s = 0.f;
    #pragma unroll 8
    for (int r = qtr * 32; r < qtr * 32 + 32; r++) {
        int t = rot_t(u * BSZ + r, rolled);
        s += kb[(size_t)t * DHq + dim];
    }
    part[threadIdx.x] = s;
    __syncthreads();
    if (threadIdx.x < 128)
        g_bsum[(size_t)blk * DHq + threadIdx.x] =
            part[threadIdx.x] + part[128 + threadIdx.x] +
            part[256 + threadIdx.x] + part[384 + threadIdx.x];
}

// ============ Kernel 2: sort scores -> (idx, val) per bucket ===============
__global__ void sort_kernel(const float* __restrict__ k,
                            const float* __restrict__ W) {
    int bh = blockIdx.x;
    int h  = bh % Hq;
    bool rolled = (h >= HHALF);
    int tid = threadIdx.x;

    __shared__ float x[BUCKETS][2*DHq];
    __shared__ float sc[BUCKETS][BUCKETS];

    const float* kb = k + (size_t)bh * Tq * DHq;

    if (tid < DHq) {
        int dim = tid;
        float run = 0.f;
        for (int u = 0; u < BUCKETS; u++) {
            int t0 = u * BSZ;
            float kfirst = kb[(size_t)rot_t(t0, rolled) * DHq + dim];
            x[u][dim]       = (run + kfirst) / (float)(t0 + 1);
            x[u][DHq + dim] = kfirst;
            run += g_bsum[((size_t)bh * BUCKETS + u) * DHq + dim];
        }
    }
    __syncthreads();

    const float* Wh = W + (size_t)h * 2 * DHq * BUCKETS;
    for (int e0 = tid; e0 < BUCKETS * BUCKETS; e0 += blockDim.x) {
        int u = e0 / BUCKETS, v = e0 % BUCKETS;
        float s = 0.f;
        #pragma unroll 4
        for (int e = 0; e < 2 * DHq; e++)
            s += x[u][e] * Wh[e * BUCKETS + v];
        sc[u][v] = (s > 0.f) ? s : 0.01f * s;
    }
    __syncthreads();

    if (tid < BUCKETS) {
        int u = tid;
        float m = -INFINITY;
        for (int v = 0; v < BUCKETS; v++) m = fmaxf(m, sc[u][v]);
        float sum = 0.f;
        for (int v = 0; v < BUCKETS; v++) sum += expf(sc[u][v] - m);
        float best = 0.f; int bi = 0;
        for (int v = 0; v < u; v++) {
            float r = expf(sc[u][v] - m) / sum;
            if (r > best) { best = r; bi = v; }
        }
        g_val[bh * BUCKETS + u] = best;
        g_idx[bh * BUCKETS + u] = bi;
    }
}

// ============ Kernel 3: fp16 ldmatrix + mma.m16n8k16 attention =============
// 2048 CTAs (2 per bucket, 64 q-rows each), 256 threads = 8 warps, 3 CTAs/SM.
// rg = wid&1 -> local rows [rg*32,+32); cg = wid>>1 (0..3).
// S warp tile: 32 rows x 16 cols (cols cg*16 within 64-key j-tile).
// O warp tile: 32 rows x 32 dims (dims cg*32).
// smem fp16 (byte offsets): Q[64][136h] | K[64][136h] | V[64][136h] |
//                           P[64][72h] | psum[256]f32 | linv[64]f32
#define QROW 272          // bytes per Q/K/V row (136 halves)
#define PROW 144          // bytes per P row (72 halves)
#define OFF_Q  0
#define OFF_K  17408
#define OFF_V  34816
#define OFF_P  52224
#define OFF_PS 61440
#define OFF_LI 62464
#define SMEM_BYTES 62720

__global__ void __launch_bounds__(256, 3)
attn_kernel(const float* __restrict__ q, const float* __restrict__ k,
            const float* __restrict__ v, float* __restrict__ out, int base) {
    extern __shared__ __align__(16) char sm[];
    uint32_t sb = smem_u32(sm);
    float* psum = (float*)(sm + OFF_PS);
    float* linv = (float*)(sm + OFF_LI);

    int gi = base + blockIdx.x;        // 0..2047
    int half = gi & 1;
    int pair = gi >> 1;
    int u  = pair % BUCKETS;
    int bh = pair / BUCKETS;
    int h  = bh % Hq;
    bool rolled  = (h >= HHALF);
    bool lastrot = rolled && (u == BUCKETS - 1);
    int ib0 = half * 64;               // absolute q-row base of this CTA

    int tid  = threadIdx.x;
    int wid  = tid >> 5;
    int l    = tid & 31;
    int rg = wid & 1;
    int cg = wid >> 1;
    int g  = l >> 2;
    int c  = l & 3;

    int   src  = g_idx[bh * BUCKETS + u];
    float sval = g_val[bh * BUCKETS + u];

    const float* qb = q + (size_t)bh * Tq * DHq;
    const float* kb = k + (size_t)bh * Tq * DHq;
    const float* vb = v + (size_t)bh * Tq * DHq;

    // ldmatrix lane address components
    int ar = (l & 7) + ((l >> 3) & 1) * 8;   // A-type / V-trans row-in-16
    int ac = (l >> 4) * 8;                   // A-type / V-trans col-sel
    int br = (l & 7) + (l >> 4) * 8;         // B(K) row-in-16
    int bc = ((l >> 3) & 1) * 8;             // B(K) col-sel
    uint32_t baseQ = sb + OFF_Q + (uint32_t)((rg * 32 + ar) * QROW + ac * 2);
    uint32_t baseK = sb + OFF_K + (uint32_t)((cg * 16 + br) * QROW + bc * 2);
    uint32_t baseV = sb + OFF_V + (uint32_t)(ar * QROW + (cg * 32 + ac) * 2);
    uint32_t baseP = sb + OFF_P + (uint32_t)((rg * 32 + ar) * PROW + ac * 2);

    // ---- stage Q (64 rows, pre-scaled into log2 domain, fp16) ----
    #pragma unroll 4
    for (int e = tid; e < 64 * 64; e += 256) {   // element = half2 pair
        int i = e >> 6, dp = e & 63;
        int tq = rot_t(u * BSZ + ib0 + i, rolled);
        float2 qv = ((const float2*)(qb + (size_t)tq * DHq))[dp];
        *(uint32_t*)(sm + OFF_Q + i * QROW + dp * 4) =
            pack_h2(qv.x * QSCALE, qv.y * QSCALE);
    }

    float accO[32];
    #pragma unroll
    for (int x = 0; x < 32; x++) accO[x] = 0.f;
    float rsum[4] = {0.f, 0.f, 0.f, 0.f};

    int ib_abs = ib0 + rg * 32;

    for (int jt = 0; jt < 4; jt++) {
        __syncthreads();
        // ---- stage K/V tile (64 keys, fp16; V row-major) ----
        #pragma unroll 4
        for (int e = tid; e < 64 * 64; e += 256) {
            int j = e >> 6, dp = e & 63;
            int jg = jt * 64 + j;
            int sbk, jj; float scl;
            if (jg < BSZ) { sbk = src; jj = jg;       scl = sval; }
            else          { sbk = u;   jj = jg - BSZ; scl = 1.f;  }
            size_t off = (size_t)rot_t(sbk * BSZ + jj, rolled) * DHq;
            float2 kv = ((const float2*)(kb + off))[dp];
            float2 vv = ((const float2*)(vb + off))[dp];
            *(uint32_t*)(sm + OFF_K + j * QROW + dp * 4) =
                pack_h2(kv.x * scl, kv.y * scl);
            *(uint32_t*)(sm + OFF_V + j * QROW + dp * 4) =
                pack_h2(vv.x * scl, vv.y * scl);
        }
        __syncthreads();

        // ---- S = Q @ K^T : warp 32x16 tile ----
        int jbw = jt * 64 + cg * 16;
        bool wskip = lastrot
            ? ((jbw + 15 <= BSZ && ib_abs > 0) || (jbw - BSZ > ib_abs + 31))
            : (jbw - BSZ > ib_abs + 31);

        float accS[16];
        #pragma unroll
        for (int x = 0; x < 16; x++) accS[x] = 0.f;

        if (!wskip) {
            #pragma unroll
            for (int ks = 0; ks < 8; ks++) {
                uint32_t aq0[4], aq1[4], bk4[4];
                ldsm4(aq0, baseQ + ks * 32);
                ldsm4(aq1, baseQ + 16 * QROW + ks * 32);
                ldsm4(bk4, baseK + ks * 32);
                mma16816(accS + 0,  aq0, bk4 + 0);
                mma16816(accS + 4,  aq0, bk4 + 2);
                mma16816(accS + 8,  aq1, bk4 + 0);
                mma16816(accS + 12, aq1, bk4 + 2);
            }
        }

        // ---- epilogue: mask + exp2, pack fp16 P, row sums ----
        #pragma unroll
        for (int mt = 0; mt < 2; mt++) {
            #pragma unroll
            for (int nt = 0; nt < 2; nt++) {
                float* ap = accS + (mt * 2 + nt) * 4;
                int ib   = ib_abs + mt * 16;
                int jmin = jbw + nt * 8;
                bool fm = lastrot
                    ? ((jmin + 7 <= BSZ && ib > 0) || (jmin - BSZ > ib + 15))
                    : (jmin - BSZ > ib + 15);
                uint32_t h01 = 0, h23 = 0;
                if (!fm) {
                    int r0 = ib + g, r1 = r0 + 8;
                    int j0 = jmin + 2 * c, j1 = j0 + 1;
                    bool v00, v01, v10, v11;
                    if (lastrot) {
                        v00 = (j0 <= BSZ) ? (r0 == 0) : (r0 >= j0 - BSZ);
                        v01 = (j1 <= BSZ) ? (r0 == 0) : (r0 >= j1 - BSZ);
                        v10 = (j0 <= BSZ) ? (r1 == 0) : (r1 >= j0 - BSZ);
                        v11 = (j1 <= BSZ) ? (r1 == 0) : (r1 >= j1 - BSZ);
                    } else {
                        v00 = (j0 < BSZ) || (r0 >= j0 - BSZ);
                        v01 = (j1 < BSZ) || (r0 >= j1 - BSZ);
                        v10 = (j0 < BSZ) || (r1 >= j0 - BSZ);
                        v11 = (j1 < BSZ) || (r1 >= j1 - BSZ);
                    }
                    float p0 = v00 ? ex2f(ap[0]) : 0.f;
                    float p1 = v01 ? ex2f(ap[1]) : 0.f;
                    float p2 = v10 ? ex2f(ap[2]) : 0.f;
                    float p3 = v11 ? ex2f(ap[3]) : 0.f;
                    h01 = pack_h2(p0, p1);
                    h23 = pack_h2(p2, p3);
                    float2 f01 = unpack_h2(h01);
                    float2 f23 = unpack_h2(h23);
                    rsum[mt * 2 + 0] += f01.x + f01.y;
                    rsum[mt * 2 + 1] += f23.x + f23.y;
                }
                int pr0 = rg * 32 + mt * 16 + g;
                int pcb = (cg * 16 + nt * 8 + 2 * c) * 2;   // byte col
                *(uint32_t*)(sm + OFF_P + pr0 * PROW + pcb)       = h01;
                *(uint32_t*)(sm + OFF_P + (pr0 + 8) * PROW + pcb) = h23;
            }
        }
        __syncthreads();

        // ---- O += P @ V : warp 32 rows x 32 dims, 4 k-steps of 16 js ----
        int jt0 = jt * 64;
        bool oskip = lastrot
            ? ((jt0 + 63 <= BSZ && ib_abs > 0) ||
               (jt0 > BSZ && jt0 - BSZ > ib_abs + 31))
            : (jt0 - BSZ > ib_abs + 31);
        if (!oskip) {
            #pragma unroll
            for (int ks = 0; ks < 4; ks++) {
                uint32_t ap0[4], ap1[4], bv0[4], bv1[4];
                ldsm4(ap0, baseP + ks * 32);
                ldsm4(ap1, baseP + 16 * PROW + ks * 32);
                ldsm4t(bv0, baseV + ks * 16 * QROW);
                ldsm4t(bv1, baseV + ks * 16 * QROW + 32);
                mma16816(accO + 0,  ap0, bv0 + 0);
                mma16816(accO + 4,  ap0, bv0 + 2);
                mma16816(accO + 8,  ap0, bv1 + 0);
                mma16816(accO + 12, ap0, bv1 + 2);
                mma16816(accO + 16, ap1, bv0 + 0);
                mma16816(accO + 20, ap1, bv0 + 2);
                mma16816(accO + 24, ap1, bv1 + 0);
                mma16816(accO + 28, ap1, bv1 + 2);
            }
        }
    }

    // ---- finalize row sums -> linv ----
    #pragma unroll
    for (int x = 0; x < 4; x++) {
        rsum[x] += __shfl_xor_sync(0xffffffffu, rsum[x], 1);
        rsum[x] += __shfl_xor_sync(0xffffffffu, rsum[x], 2);
    }
    __syncthreads();
    if (c == 0) {
        #pragma unroll
        for (int x = 0; x < 4; x++) {
            int lr = rg * 32 + (x >> 1) * 16 + g + (x & 1) * 8;
            psum[cg * 64 + lr] = rsum[x];
        }
    }
    __syncthreads();
    if (tid < 64)
        linv[tid] = 1.f / (psum[tid] + psum[64 + tid] +
                           psum[128 + tid] + psum[192 + tid]);
    __syncthreads();

    // ---- normalize + store (rotation folded into scatter) ----
    float* ob = out + (size_t)bh * Tq * DHq;
    #pragma unroll
    for (int mt = 0; mt < 2; mt++) {
        int lr0 = rg * 32 + mt * 16 + g;
        float il0 = linv[lr0];
        float il1 = linv[lr0 + 8];
        int t0 = rot_t(u * BSZ + ib0 + lr0, rolled);
        int t1 = rot_t(u * BSZ + ib0 + lr0 + 8, rolled);
        #pragma unroll
        for (int d8 = 0; d8 < 4; d8++) {
            float* ap = accO + (mt * 4 + d8) * 4;
            int d = cg * 32 + d8 * 8 + 2 * c;
            *(float2*)&ob[(size_t)t0 * DHq + d] =
                make_float2(ap[0] * il0, ap[1] * il0);
            *(float2*)&ob[(size_t)t1 * DHq + d] =
                make_float2(ap[2] * il1, ap[3] * il1);
        }
    }
}

// ================================ launch ===================================
extern "C" void kernel_launch(void* const* d_in, const int* in_sizes, int n_in,
                              void* d_out, int out_size) {
    const float* q = (const float*)d_in[0];
    const float* k = (const float*)d_in[1];
    const float* v = (const float*)d_in[2];
    const float* W = (const float*)d_in[3];
    float* out = (float*)d_out;

    cudaFuncSetAttribute(attn_kernel,
                         cudaFuncAttributeMaxDynamicSharedMemorySize, SMEM_BYTES);

    bucket_sum_kernel<<<Bq*Hq*BUCKETS, 512>>>(k);
    sort_kernel<<<Bq*Hq, 256>>>(k, W);
    // 4 launches/replay keeps an attn launch at ncu's capture index (6 mod 4 = 2)
    attn_kernel<<<1024, 256, SMEM_BYTES>>>(q, k, v, out, 0);
    attn_kernel<<<1024, 256, SMEM_BYTES>>>(q, k, v, out, 1024);
}